// round 6
// baseline (speedup 1.0000x reference)
#include <cuda_runtime.h>
#include <cuda_fp16.h>
#include <cstdint>
#include <cstddef>

#define DI __device__ __forceinline__

// ---------------- problem constants ----------------
constexpr int BATCH = 4096;
constexpr int INF   = 1024;
constexpr int OUTF  = 1024;
constexpr int KSP   = INF * 8;       // 8192 spline K
constexpr int KTOT  = KSP + INF;     // 9216 total K
constexpr int KBLK  = 64;            // fp16 per K-tile -> 128 B rows (SW128)
constexpr int NKT   = KTOT / KBLK;   // 144 K-tiles
constexpr int NKT_SP = KSP / KBLK;   // 128 spline K-tiles
constexpr int TM    = 128;
constexpr int TN    = 256;
constexpr int MT    = BATCH / TM;    // 32
constexpr int NT    = OUTF / TN;     // 4
constexpr int STAGES = 4;
constexpr int A_TILE_B = TM * KBLK * 2;       // 16384
constexpr int B_TILE_B = TN * KBLK * 2;       // 32768
constexpr int STAGE_B  = A_TILE_B + B_TILE_B; // 49152

constexpr int NTHREADS  = 320;   // 8 consumer warps + 2 producer warps
constexpr int NCONSUMER = 256;
constexpr int NPRODUCER = 64;

constexpr int SOFF_FULL  = 0;    // 4 x 8B
constexpr int SOFF_EMPTY = 32;   // 4 x 8B
constexpr int SOFF_STAGE = 1024;
constexpr int SMEM_NEED  = 1024 + SOFF_STAGE + STAGES * STAGE_B; // 198656 < 227KB cap

// ---------------- scratch (device globals; no allocation) ----------------
__device__ __half g_B[(size_t)NT * NKT * TN * KBLK];  // 18.9 MB tiled+swizzled weights

// ---------------- PTX helpers ----------------
DI uint32_t s2u(const void* p) {
    uint32_t a;
    asm("{ .reg .u64 t; cvta.to.shared.u64 t, %1; cvt.u32.u64 %0, t; }" : "=r"(a) : "l"(p));
    return a;
}
DI uint32_t swz(uint32_t off) { return off ^ ((off >> 3) & 0x70); }

DI void sts128(uint32_t addr, uint4 v) {
    asm volatile("st.shared.v4.b32 [%0], {%1,%2,%3,%4};"
                 :: "r"(addr), "r"(v.x), "r"(v.y), "r"(v.z), "r"(v.w) : "memory");
}

DI void mbar_init(uint32_t a, uint32_t cnt) {
    asm volatile("mbarrier.init.shared.b64 [%0], %1;" :: "r"(a), "r"(cnt) : "memory");
}
DI void mbar_arrive(uint32_t a) {
    asm volatile("mbarrier.arrive.release.cta.shared.b64 _, [%0];" :: "r"(a) : "memory");
}
DI void mbar_expect_tx_only(uint32_t a, uint32_t bytes) {  // no arrive
    asm volatile("mbarrier.expect_tx.relaxed.cta.shared::cta.b64 [%0], %1;"
                 :: "r"(a), "r"(bytes) : "memory");
}
DI void mbar_wait(uint32_t a, uint32_t parity) {
    asm volatile(
        "{\n\t"
        ".reg .pred P1;\n\t"
        "WAIT_LOOP_%=:\n\t"
        "mbarrier.try_wait.parity.acquire.cta.shared::cta.b64 P1, [%0], %1, 0x989680;\n\t"
        "@P1 bra.uni WAIT_DONE_%=;\n\t"
        "bra.uni WAIT_LOOP_%=;\n\t"
        "WAIT_DONE_%=:\n\t"
        "}"
        :: "r"(a), "r"(parity) : "memory");
}
DI void bulk_g2s(uint32_t dst, const void* src, uint32_t bytes, uint32_t mbar) {
    asm volatile(
        "cp.async.bulk.shared::cluster.global.mbarrier::complete_tx::bytes [%0], [%1], %2, [%3];"
        :: "r"(dst), "l"(src), "r"(bytes), "r"(mbar) : "memory");
}
DI void ldsm4(uint32_t* r, uint32_t addr) {
    asm volatile("ldmatrix.sync.aligned.m8n8.x4.shared.b16 {%0,%1,%2,%3}, [%4];"
                 : "=r"(r[0]), "=r"(r[1]), "=r"(r[2]), "=r"(r[3]) : "r"(addr));
}
DI void mma_f16(float* c, const uint32_t* a, uint32_t b0, uint32_t b1) {
    asm volatile(
        "mma.sync.aligned.m16n8k16.row.col.f32.f16.f16.f32 "
        "{%0,%1,%2,%3}, {%4,%5,%6,%7}, {%8,%9}, {%0,%1,%2,%3};"
        : "+f"(c[0]), "+f"(c[1]), "+f"(c[2]), "+f"(c[3])
        : "r"(a[0]), "r"(a[1]), "r"(a[2]), "r"(a[3]), "r"(b0), "r"(b1));
}

// ---- Cox-de-Boor bases for one scalar x -> 8 fp16 values packed as uint4 ----
DI uint4 bases8_fp16(float xv) {
    float t = 1.0f - __fdividef(2.0f, __expf(2.0f * xv) + 1.0f);  // tanh

    float g[12];
#pragma unroll
    for (int j = 0; j < 12; j++) g[j] = fmaf(0.4f, (float)j, -2.2f);

    constexpr float R1 = 1.0f / (0.4f + 1e-8f);
    constexpr float R2 = 1.0f / (0.8f + 1e-8f);
    constexpr float R3 = 1.0f / (1.2f + 1e-8f);
    const float RK[3] = {R1, R2, R3};

    float bas[11];
#pragma unroll
    for (int n = 0; n < 11; n++) bas[n] = (t >= g[n] && t < g[n + 1]) ? 1.0f : 0.0f;

#pragma unroll
    for (int k = 1; k <= 3; k++) {
        float rk = RK[k - 1];
#pragma unroll
        for (int j = 0; j < 11 - k; j++) {
            float left  = (t - g[j]) * rk;
            float right = (g[j + k + 1] - t) * rk;
            bas[j] = left * bas[j] + right * bas[j + 1];
        }
    }
    __half hv[8];
#pragma unroll
    for (int n = 0; n < 8; n++) hv[n] = __float2half_rn(bas[n]);
    return *reinterpret_cast<uint4*>(hv);
}

DI uint4 silu8_fp16(float4 a, float4 b) {
    __half hv[8];
    hv[0] = __float2half_rn(__fdividef(a.x, 1.0f + __expf(-a.x)));
    hv[1] = __float2half_rn(__fdividef(a.y, 1.0f + __expf(-a.y)));
    hv[2] = __float2half_rn(__fdividef(a.z, 1.0f + __expf(-a.z)));
    hv[3] = __float2half_rn(__fdividef(a.w, 1.0f + __expf(-a.w)));
    hv[4] = __float2half_rn(__fdividef(b.x, 1.0f + __expf(-b.x)));
    hv[5] = __float2half_rn(__fdividef(b.y, 1.0f + __expf(-b.y)));
    hv[6] = __float2half_rn(__fdividef(b.z, 1.0f + __expf(-b.z)));
    hv[7] = __float2half_rn(__fdividef(b.w, 1.0f + __expf(-b.w)));
    return *reinterpret_cast<uint4*>(hv);
}

// ---------------- prologue B: re-tile + swizzle weights to fp16 ----------------
__global__ void __launch_bounds__(256) prolog_b(const float* __restrict__ spw,
                                                const float* __restrict__ baw) {
    int idx = blockIdx.x * 256 + threadIdx.x;
    int o  = idx / (KTOT / 8);
    int kq = idx % (KTOT / 8);
    int k  = kq * 8;
    float4 v0, v1;
    if (k < KSP) {
        const float4* p = reinterpret_cast<const float4*>(spw + (size_t)o * KSP + k);
        v0 = p[0]; v1 = p[1];
    } else {
        const float4* p = reinterpret_cast<const float4*>(baw + (size_t)o * INF + (k - KSP));
        v0 = p[0]; v1 = p[1];
    }
    __half hv[8];
    hv[0] = __float2half_rn(v0.x); hv[1] = __float2half_rn(v0.y);
    hv[2] = __float2half_rn(v0.z); hv[3] = __float2half_rn(v0.w);
    hv[4] = __float2half_rn(v1.x); hv[5] = __float2half_rn(v1.y);
    hv[6] = __float2half_rn(v1.z); hv[7] = __float2half_rn(v1.w);

    int nt = o >> 8, row = o & 255;
    int kt = k >> 6;
    size_t tile = ((size_t)(nt * NKT + kt)) * B_TILE_B;
    uint32_t off = (uint32_t)(row * 128 + (k & 63) * 2);
    *reinterpret_cast<uint4*>((char*)g_B + tile + swz(off)) = *reinterpret_cast<uint4*>(hv);
}

// ---------------- fused GEMM: producer warps + consumer warps ----------------
__global__ void __launch_bounds__(NTHREADS, 1) kan_gemm(float* __restrict__ out,
                                                        const float* __restrict__ x) {
    extern __shared__ __align__(16) char smem_raw[];
    uint32_t sb = (s2u(smem_raw) + 1023u) & ~1023u;
    int tid = threadIdx.x, wid = tid >> 5, lane = tid & 31;

    if (tid == 0) {
        for (int s = 0; s < STAGES; s++) {
            mbar_init(sb + SOFF_FULL  + 8 * s, NPRODUCER);   // 64 producer arrivals + tx
            mbar_init(sb + SOFF_EMPTY + 8 * s, NCONSUMER);   // 256 consumer arrivals
        }
    }
    __syncthreads();

    int mt = blockIdx.x, nt = blockIdx.y;

    if (wid >= 8) {
        // ================= PRODUCER (warps 8-9, 64 lanes) =================
        int ptid = tid - NCONSUMER;             // 0..63
        const char* bgl = (const char*)g_B + (size_t)nt * NKT * B_TILE_B;
        int r0 = ptid * 2;                      // two rows per lane
        const float* xr0 = x + (size_t)(mt * 128 + r0) * INF;
        const float* xr1 = xr0 + INF;
        int ephase = 0;

#pragma unroll 1
        for (int j = 0; j < NKT; j++) {
            int s = j & (STAGES - 1);
            uint32_t full  = sb + SOFF_FULL + 8 * s;
            uint32_t sa    = sb + SOFF_STAGE + s * STAGE_B;
            if (j >= STAGES) {
                mbar_wait(sb + SOFF_EMPTY + 8 * s, ephase);
                if (s == STAGES - 1) ephase ^= 1;
            }
            // kick B copy early so it overlaps basis compute
            if (ptid == 0) {
                mbar_expect_tx_only(full, B_TILE_B);
                bulk_g2s(sa + A_TILE_B, bgl + (size_t)j * B_TILE_B, B_TILE_B, full);
            }

            if (j < NKT_SP) {
                // spline tile: i in [8j, 8j+8); this lane covers rows r0, r0+1
                float4 a0 = *reinterpret_cast<const float4*>(xr0 + j * 8);
                float4 a1 = *reinterpret_cast<const float4*>(xr0 + j * 8 + 4);
                float4 b0 = *reinterpret_cast<const float4*>(xr1 + j * 8);
                float4 b1 = *reinterpret_cast<const float4*>(xr1 + j * 8 + 4);
                uint32_t base0 = (uint32_t)(r0 * 128);
                uint32_t base1 = base0 + 128;
                sts128(sa + swz(base0 +  0), bases8_fp16(a0.x));
                sts128(sa + swz(base0 + 16), bases8_fp16(a0.y));
                sts128(sa + swz(base0 + 32), bases8_fp16(a0.z));
                sts128(sa + swz(base0 + 48), bases8_fp16(a0.w));
                sts128(sa + swz(base0 + 64), bases8_fp16(a1.x));
                sts128(sa + swz(base0 + 80), bases8_fp16(a1.y));
                sts128(sa + swz(base0 + 96), bases8_fp16(a1.z));
                sts128(sa + swz(base0 +112), bases8_fp16(a1.w));
                sts128(sa + swz(base1 +  0), bases8_fp16(b0.x));
                sts128(sa + swz(base1 + 16), bases8_fp16(b0.y));
                sts128(sa + swz(base1 + 32), bases8_fp16(b0.z));
                sts128(sa + swz(base1 + 48), bases8_fp16(b0.w));
                sts128(sa + swz(base1 + 64), bases8_fp16(b1.x));
                sts128(sa + swz(base1 + 80), bases8_fp16(b1.y));
                sts128(sa + swz(base1 + 96), bases8_fp16(b1.z));
                sts128(sa + swz(base1 +112), bases8_fp16(b1.w));
            } else {
                // silu tile: i in [64(j-128), +64); 2 rows x 8 octets per lane
                int ib = (j - NKT_SP) * 64;
#pragma unroll
                for (int rr = 0; rr < 2; rr++) {
                    const float* xr = rr ? xr1 : xr0;
                    uint32_t rbase = (uint32_t)((r0 + rr) * 128);
#pragma unroll
                    for (int oc = 0; oc < 8; oc++) {
                        const float4* p = reinterpret_cast<const float4*>(xr + ib + oc * 8);
                        sts128(sa + swz(rbase + oc * 16), silu8_fp16(p[0], p[1]));
                    }
                }
            }
            mbar_arrive(full);   // release: after this lane's stores
        }
        return;
    }

    // ================= CONSUMER (warps 0-7, 256 lanes) =================
    int warp_m = wid >> 2, warp_n = wid & 3;   // 2 x 4 warp grid, 64x64 per warp

    // ---- per-thread ldmatrix addressing (swizzle-folded) ----
    int g = lane >> 3, r = lane & 7;
    int rA = warp_m * 64 + (g & 1) * 8 + r;
    uint32_t acol0 = (uint32_t)((g >> 1) * 16);
    uint32_t amask = (uint32_t)((rA & 7) << 4);
    int rB = warp_n * 64 + ((g >> 1) & 1) * 8 + r;
    uint32_t bcol0 = (uint32_t)((g & 1) * 16);
    uint32_t bmask = (uint32_t)((rB & 7) << 4);
    uint32_t acol[4], bcol[4];
#pragma unroll
    for (int ks = 0; ks < 4; ks++) {
        acol[ks] = (acol0 + ks * 32) ^ amask;
        bcol[ks] = (bcol0 + ks * 32) ^ bmask;
    }
    uint32_t aRowOff = (uint32_t)(rA * 128);
    uint32_t bRowOff = (uint32_t)(A_TILE_B + rB * 128);

    float acc[4][8][4];
#pragma unroll
    for (int mi = 0; mi < 4; mi++)
#pragma unroll
        for (int nj = 0; nj < 8; nj++)
#pragma unroll
            for (int q = 0; q < 4; q++) acc[mi][nj][q] = 0.0f;

    int fphase = 0;
#pragma unroll 1
    for (int kt = 0; kt < NKT; kt++) {
        int s = kt & (STAGES - 1);
        mbar_wait(sb + SOFF_FULL + 8 * s, fphase);
        if (s == STAGES - 1) fphase ^= 1;

        uint32_t sbase = sb + SOFF_STAGE + s * STAGE_B;
        uint32_t baseA = sbase + aRowOff;
        uint32_t baseB = sbase + bRowOff;

#pragma unroll
        for (int ks = 0; ks < 4; ks++) {
            uint32_t af[4][4], bf[4][4];
#pragma unroll
            for (int mi = 0; mi < 4; mi++) ldsm4(af[mi], baseA + mi * 2048 + acol[ks]);
#pragma unroll
            for (int np = 0; np < 4; np++) ldsm4(bf[np], baseB + np * 2048 + bcol[ks]);
#pragma unroll
            for (int mi = 0; mi < 4; mi++)
#pragma unroll
                for (int nj = 0; nj < 8; nj++)
                    mma_f16(acc[mi][nj], af[mi],
                            bf[nj >> 1][(nj & 1) * 2], bf[nj >> 1][(nj & 1) * 2 + 1]);
        }
        mbar_arrive(sb + SOFF_EMPTY + 8 * s);
    }

    // ---- epilogue: FP32 accumulators -> global ----
    int row0 = mt * 128 + warp_m * 64 + (lane >> 2);
    int col0 = nt * 256 + warp_n * 64 + (lane & 3) * 2;
#pragma unroll
    for (int mi = 0; mi < 4; mi++) {
#pragma unroll
        for (int nj = 0; nj < 8; nj++) {
            float* p0 = out + (size_t)(row0 + mi * 16) * OUTF + col0 + nj * 8;
            float* p1 = out + (size_t)(row0 + mi * 16 + 8) * OUTF + col0 + nj * 8;
            *reinterpret_cast<float2*>(p0) = make_float2(acc[mi][nj][0], acc[mi][nj][1]);
            *reinterpret_cast<float2*>(p1) = make_float2(acc[mi][nj][2], acc[mi][nj][3]);
        }
    }
}

// ---------------- host launch ----------------
extern "C" void kernel_launch(void* const* d_in, const int* in_sizes, int n_in,
                              void* d_out, int out_size) {
    (void)in_sizes; (void)n_in; (void)out_size;
    const float* x   = (const float*)d_in[0];
    const float* spw = (const float*)d_in[1];
    const float* baw = (const float*)d_in[2];
    float* out = (float*)d_out;

    prolog_b<<<(OUTF * (KTOT / 8)) / 256, 256>>>(spw, baw);

    static int smem_set = 0;
    if (!smem_set) {
        cudaFuncSetAttribute(kan_gemm, cudaFuncAttributeMaxDynamicSharedMemorySize, SMEM_NEED);
        smem_set = 1;
    }
    kan_gemm<<<dim3(MT, NT), NTHREADS, SMEM_NEED>>>(out, x);
}

// round 7
// speedup vs baseline: 3.2123x; 3.2123x over previous
#include <cuda_runtime.h>
#include <cuda_fp16.h>
#include <cstdint>
#include <cstddef>

#define DI __device__ __forceinline__

// ---------------- problem constants ----------------
constexpr int BATCH = 4096;
constexpr int INF   = 1024;
constexpr int OUTF  = 1024;
constexpr int KSP   = INF * 8;       // 8192 spline K
constexpr int KTOT  = KSP + INF;     // 9216 total K
constexpr int KBLK  = 64;            // fp16 per K-tile -> 128 B rows (SW128)
constexpr int NKT   = KTOT / KBLK;   // 144 K-tiles
constexpr int TM    = 128;
constexpr int TN    = 256;
constexpr int MT    = BATCH / TM;    // 32
constexpr int NT    = OUTF / TN;     // 4
constexpr int STAGES = 4;
constexpr int A_TILE_B = TM * KBLK * 2;       // 16384
constexpr int B_TILE_B = TN * KBLK * 2;       // 32768
constexpr int STAGE_B  = A_TILE_B + B_TILE_B; // 49152

constexpr int SOFF_FULL  = 0;    // 4 x 8B
constexpr int SOFF_EMPTY = 32;   // 4 x 8B
constexpr int SOFF_STAGE = 1024;
constexpr int SMEM_NEED  = 1024 + SOFF_STAGE + STAGES * STAGE_B; // 198656 < 227KB cap

constexpr int BLOCKS_A = (BATCH * INF) / 256;       // 16384
constexpr int BLOCKS_B = (OUTF * (KTOT / 8)) / 256; // 4608

// ---------------- scratch (device globals; no allocation) ----------------
__device__ __half g_A[(size_t)MT * NKT * TM * KBLK];  // 75.5 MB tiled+swizzled activations
__device__ __half g_B[(size_t)NT * NKT * TN * KBLK];  // 18.9 MB tiled+swizzled weights

// ---------------- PTX helpers ----------------
DI uint32_t s2u(const void* p) {
    uint32_t a;
    asm("{ .reg .u64 t; cvta.to.shared.u64 t, %1; cvt.u32.u64 %0, t; }" : "=r"(a) : "l"(p));
    return a;
}
DI uint32_t swz(uint32_t off) { return off ^ ((off >> 3) & 0x70); }

DI void mbar_init(uint32_t a, uint32_t cnt) {
    asm volatile("mbarrier.init.shared.b64 [%0], %1;" :: "r"(a), "r"(cnt) : "memory");
}
DI void mbar_arrive(uint32_t a) {
    asm volatile("mbarrier.arrive.release.cta.shared.b64 _, [%0];" :: "r"(a) : "memory");
}
DI void mbar_expect_tx(uint32_t a, uint32_t bytes) {
    asm volatile("mbarrier.arrive.expect_tx.shared.b64 _, [%0], %1;" :: "r"(a), "r"(bytes) : "memory");
}
DI void mbar_wait(uint32_t a, uint32_t parity) {
    asm volatile(
        "{\n\t"
        ".reg .pred P1;\n\t"
        "WAIT_LOOP_%=:\n\t"
        "mbarrier.try_wait.parity.acquire.cta.shared::cta.b64 P1, [%0], %1, 0x989680;\n\t"
        "@P1 bra.uni WAIT_DONE_%=;\n\t"
        "bra.uni WAIT_LOOP_%=;\n\t"
        "WAIT_DONE_%=:\n\t"
        "}"
        :: "r"(a), "r"(parity) : "memory");
}
DI void bulk_g2s(uint32_t dst, const void* src, uint32_t bytes, uint32_t mbar) {
    asm volatile(
        "cp.async.bulk.shared::cluster.global.mbarrier::complete_tx::bytes [%0], [%1], %2, [%3];"
        :: "r"(dst), "l"(src), "r"(bytes), "r"(mbar) : "memory");
}
DI void ldsm4(uint32_t* r, uint32_t addr) {
    asm volatile("ldmatrix.sync.aligned.m8n8.x4.shared.b16 {%0,%1,%2,%3}, [%4];"
                 : "=r"(r[0]), "=r"(r[1]), "=r"(r[2]), "=r"(r[3]) : "r"(addr));
}
DI void mma_f16(float* c, const uint32_t* a, uint32_t b0, uint32_t b1) {
    asm volatile(
        "mma.sync.aligned.m16n8k16.row.col.f32.f16.f16.f32 "
        "{%0,%1,%2,%3}, {%4,%5,%6,%7}, {%8,%9}, {%0,%1,%2,%3};"
        : "+f"(c[0]), "+f"(c[1]), "+f"(c[2]), "+f"(c[3])
        : "r"(a[0]), "r"(a[1]), "r"(a[2]), "r"(a[3]), "r"(b0), "r"(b1));
}

// ---------------- merged prologue: A (bases+silu) and B (weight retile) ----------------
__global__ void __launch_bounds__(256) prolog_ab(const float* __restrict__ x,
                                                 const float* __restrict__ spw,
                                                 const float* __restrict__ baw) {
    if (blockIdx.x < BLOCKS_A) {
        // ----- part A: one (b, i) per thread -----
        int idx = blockIdx.x * 256 + threadIdx.x;
        int b = idx >> 10;
        int i = idx & 1023;
        float xv = x[idx];

        // tanh(x) = 1 - 2/(e^{2x}+1)
        float t = 1.0f - __fdividef(2.0f, __expf(2.0f * xv) + 1.0f);

        float g[12];
#pragma unroll
        for (int j = 0; j < 12; j++) g[j] = fmaf(0.4f, (float)j, -2.2f);

        constexpr float R1 = 1.0f / (0.4f + 1e-8f);
        constexpr float R2 = 1.0f / (0.8f + 1e-8f);
        constexpr float R3 = 1.0f / (1.2f + 1e-8f);
        const float RK[3] = {R1, R2, R3};

        float bas[11];
#pragma unroll
        for (int n = 0; n < 11; n++) bas[n] = (t >= g[n] && t < g[n + 1]) ? 1.0f : 0.0f;

#pragma unroll
        for (int k = 1; k <= 3; k++) {
            float rk = RK[k - 1];
#pragma unroll
            for (int j = 0; j < 11 - k; j++) {
                float left  = (t - g[j]) * rk;
                float right = (g[j + k + 1] - t) * rk;
                bas[j] = left * bas[j] + right * bas[j + 1];
            }
        }

        int mt = b >> 7, row = b & 127;
        char* abase = (char*)g_A;
        {
            int kt = i >> 3;
            size_t tile = ((size_t)(mt * NKT + kt)) * A_TILE_B;
            uint32_t off = (uint32_t)(row * 128 + (i & 7) * 16);
            __half hv[8];
#pragma unroll
            for (int n = 0; n < 8; n++) hv[n] = __float2half_rn(bas[n]);
            *reinterpret_cast<uint4*>(abase + tile + swz(off)) = *reinterpret_cast<uint4*>(hv);
        }
        {
            float sl = __fdividef(xv, 1.0f + __expf(-xv));
            int kt = 128 + (i >> 6);
            size_t tile = ((size_t)(mt * NKT + kt)) * A_TILE_B;
            uint32_t off = (uint32_t)(row * 128 + (i & 63) * 2);
            *reinterpret_cast<__half*>(abase + tile + swz(off)) = __float2half_rn(sl);
        }
    } else {
        // ----- part B: one group of 8 K-floats per thread -----
        int idx = (blockIdx.x - BLOCKS_A) * 256 + threadIdx.x;
        int o  = idx / (KTOT / 8);
        int kq = idx % (KTOT / 8);
        int k  = kq * 8;
        float4 v0, v1;
        if (k < KSP) {
            const float4* p = reinterpret_cast<const float4*>(spw + (size_t)o * KSP + k);
            v0 = p[0]; v1 = p[1];
        } else {
            const float4* p = reinterpret_cast<const float4*>(baw + (size_t)o * INF + (k - KSP));
            v0 = p[0]; v1 = p[1];
        }
        __half hv[8];
        hv[0] = __float2half_rn(v0.x); hv[1] = __float2half_rn(v0.y);
        hv[2] = __float2half_rn(v0.z); hv[3] = __float2half_rn(v0.w);
        hv[4] = __float2half_rn(v1.x); hv[5] = __float2half_rn(v1.y);
        hv[6] = __float2half_rn(v1.z); hv[7] = __float2half_rn(v1.w);

        int nt = o >> 8, row = o & 255;
        int kt = k >> 6;
        size_t tile = ((size_t)(nt * NKT + kt)) * B_TILE_B;
        uint32_t off = (uint32_t)(row * 128 + (k & 63) * 2);
        *reinterpret_cast<uint4*>((char*)g_B + tile + swz(off)) = *reinterpret_cast<uint4*>(hv);
    }
}

// ---------------- GEMM: mma.sync fp16, CTA 128x256, 4-stage bulk pipeline ----------------
__global__ void __launch_bounds__(256, 1) kan_gemm(float* __restrict__ out) {
    extern __shared__ __align__(16) char smem_raw[];
    uint32_t sb = (s2u(smem_raw) + 1023u) & ~1023u;
    int tid = threadIdx.x, wid = tid >> 5, lane = tid & 31;
    int warp_m = wid >> 2, warp_n = wid & 3;   // 2 x 4 warp grid, 64x64 per warp

    if (tid == 0) {
        for (int s = 0; s < STAGES; s++) {
            mbar_init(sb + SOFF_FULL  + 8 * s, 1);
            mbar_init(sb + SOFF_EMPTY + 8 * s, 256);
        }
    }
    __syncthreads();

    int mt = blockIdx.x, nt = blockIdx.y;
    const char* agl = (const char*)g_A + (size_t)mt * NKT * A_TILE_B;
    const char* bgl = (const char*)g_B + (size_t)nt * NKT * B_TILE_B;

    // ---- per-thread ldmatrix addressing (swizzle-folded) ----
    int g = lane >> 3, r = lane & 7;
    int rA = warp_m * 64 + (g & 1) * 8 + r;
    uint32_t acol0 = (uint32_t)((g >> 1) * 16);
    uint32_t amask = (uint32_t)((rA & 7) << 4);
    int rB = warp_n * 64 + ((g >> 1) & 1) * 8 + r;
    uint32_t bcol0 = (uint32_t)((g & 1) * 16);
    uint32_t bmask = (uint32_t)((rB & 7) << 4);
    uint32_t acol[4], bcol[4];
#pragma unroll
    for (int ks = 0; ks < 4; ks++) {
        acol[ks] = (acol0 + ks * 32) ^ amask;
        bcol[ks] = (bcol0 + ks * 32) ^ bmask;
    }
    uint32_t aRowOff = (uint32_t)(rA * 128);
    uint32_t bRowOff = (uint32_t)(A_TILE_B + rB * 128);

    float acc[4][8][4];
#pragma unroll
    for (int mi = 0; mi < 4; mi++)
#pragma unroll
        for (int nj = 0; nj < 8; nj++)
#pragma unroll
            for (int q = 0; q < 4; q++) acc[mi][nj][q] = 0.0f;

    // ---- prefetch first STAGES-1 tiles ----
    if (tid == 0) {
#pragma unroll
        for (int p = 0; p < STAGES - 1; p++) {
            uint32_t full = sb + SOFF_FULL + 8 * p;
            mbar_expect_tx(full, STAGE_B);
            uint32_t sa = sb + SOFF_STAGE + p * STAGE_B;
            bulk_g2s(sa,            agl + (size_t)p * A_TILE_B, A_TILE_B, full);
            bulk_g2s(sa + A_TILE_B, bgl + (size_t)p * B_TILE_B, B_TILE_B, full);
        }
    }

    int fphase = 0, ephase = 0;
#pragma unroll 1
    for (int kt = 0; kt < NKT; kt++) {
        if (tid == 0) {
            int j = kt + STAGES - 1;
            if (j < NKT) {
                int sp = j % STAGES;
                if (j >= STAGES) {
                    mbar_wait(sb + SOFF_EMPTY + 8 * sp, ephase);
                    if (sp == STAGES - 1) ephase ^= 1;
                }
                uint32_t full = sb + SOFF_FULL + 8 * sp;
                mbar_expect_tx(full, STAGE_B);
                uint32_t sa = sb + SOFF_STAGE + sp * STAGE_B;
                bulk_g2s(sa,            agl + (size_t)j * A_TILE_B, A_TILE_B, full);
                bulk_g2s(sa + A_TILE_B, bgl + (size_t)j * B_TILE_B, B_TILE_B, full);
            }
        }
        int s = kt % STAGES;
        mbar_wait(sb + SOFF_FULL + 8 * s, fphase);
        if (s == STAGES - 1) fphase ^= 1;

        uint32_t sbase = sb + SOFF_STAGE + s * STAGE_B;
        uint32_t baseA = sbase + aRowOff;
        uint32_t baseB = sbase + bRowOff;
#pragma unroll
        for (int ks = 0; ks < 4; ks++) {
            uint32_t af[4][4], bf[4][4];
#pragma unroll
            for (int mi = 0; mi < 4; mi++) ldsm4(af[mi], baseA + mi * 2048 + acol[ks]);
#pragma unroll
            for (int np = 0; np < 4; np++) ldsm4(bf[np], baseB + np * 2048 + bcol[ks]);
            // Early release: after the LAST ldmatrix of this ktile the stage's
            // smem is dead for this thread — let the producer refill it while
            // the final MMA batch drains.
            if (ks == 3) mbar_arrive(sb + SOFF_EMPTY + 8 * s);
#pragma unroll
            for (int mi = 0; mi < 4; mi++)
#pragma unroll
                for (int nj = 0; nj < 8; nj++)
                    mma_f16(acc[mi][nj], af[mi],
                            bf[nj >> 1][(nj & 1) * 2], bf[nj >> 1][(nj & 1) * 2 + 1]);
        }
    }

    // ---- epilogue: FP32 accumulators -> global ----
    int row0 = mt * 128 + warp_m * 64 + (lane >> 2);
    int col0 = nt * 256 + warp_n * 64 + (lane & 3) * 2;
#pragma unroll
    for (int mi = 0; mi < 4; mi++) {
#pragma unroll
        for (int nj = 0; nj < 8; nj++) {
            float* p0 = out + (size_t)(row0 + mi * 16) * OUTF + col0 + nj * 8;
            float* p1 = out + (size_t)(row0 + mi * 16 + 8) * OUTF + col0 + nj * 8;
            *reinterpret_cast<float2*>(p0) = make_float2(acc[mi][nj][0], acc[mi][nj][1]);
            *reinterpret_cast<float2*>(p1) = make_float2(acc[mi][nj][2], acc[mi][nj][3]);
        }
    }
}

// ---------------- host launch ----------------
extern "C" void kernel_launch(void* const* d_in, const int* in_sizes, int n_in,
                              void* d_out, int out_size) {
    (void)in_sizes; (void)n_in; (void)out_size;
    const float* x   = (const float*)d_in[0];
    const float* spw = (const float*)d_in[1];
    const float* baw = (const float*)d_in[2];
    float* out = (float*)d_out;

    prolog_ab<<<BLOCKS_A + BLOCKS_B, 256>>>(x, spw, baw);

    static int smem_set = 0;
    if (!smem_set) {
        cudaFuncSetAttribute(kan_gemm, cudaFuncAttributeMaxDynamicSharedMemorySize, SMEM_NEED);
        smem_set = 1;
    }
    kan_gemm<<<dim3(MT, NT), 256, SMEM_NEED>>>(out);
}

// round 8
// speedup vs baseline: 3.2159x; 1.0011x over previous
#include <cuda_runtime.h>
#include <cuda_fp16.h>
#include <cstdint>
#include <cstddef>

#define DI __device__ __forceinline__

// ---------------- problem constants ----------------
constexpr int BATCH = 4096;
constexpr int INF   = 1024;
constexpr int OUTF  = 1024;
constexpr int KSP   = INF * 8;       // 8192 spline K
constexpr int KTOT  = KSP + INF;     // 9216 total K
constexpr int KBLK  = 64;            // fp16 per K-tile -> 128 B rows (SW128)
constexpr int NKT   = KTOT / KBLK;   // 144 K-tiles
constexpr int TM    = 128;
constexpr int TN    = 128;           // halved: 2 CTAs/SM to hide pipeline bubbles
constexpr int MT    = BATCH / TM;    // 32
constexpr int NT    = OUTF / TN;     // 8
constexpr int STAGES = 3;
constexpr int A_TILE_B = TM * KBLK * 2;       // 16384
constexpr int B_TILE_B = TN * KBLK * 2;       // 16384
constexpr int STAGE_B  = A_TILE_B + B_TILE_B; // 32768

constexpr int SOFF_FULL  = 0;    // 3 x 8B
constexpr int SOFF_EMPTY = 32;   // 3 x 8B
constexpr int SOFF_STAGE = 1024;
constexpr int SMEM_NEED  = 1024 + SOFF_STAGE + STAGES * STAGE_B; // 100352; x2 CTAs < 228KB

constexpr int BLOCKS_A = (BATCH * INF) / 256;       // 16384
constexpr int BLOCKS_B = (OUTF * (KTOT / 8)) / 256; // 4608

// ---------------- scratch (device globals; no allocation) ----------------
__device__ __half g_A[(size_t)MT * NKT * TM * KBLK];  // 75.5 MB tiled+swizzled activations
__device__ __half g_B[(size_t)NT * NKT * TN * KBLK];  // 18.9 MB tiled+swizzled weights

// ---------------- PTX helpers ----------------
DI uint32_t s2u(const void* p) {
    uint32_t a;
    asm("{ .reg .u64 t; cvta.to.shared.u64 t, %1; cvt.u32.u64 %0, t; }" : "=r"(a) : "l"(p));
    return a;
}
DI uint32_t swz(uint32_t off) { return off ^ ((off >> 3) & 0x70); }

DI void mbar_init(uint32_t a, uint32_t cnt) {
    asm volatile("mbarrier.init.shared.b64 [%0], %1;" :: "r"(a), "r"(cnt) : "memory");
}
DI void mbar_arrive(uint32_t a) {
    asm volatile("mbarrier.arrive.release.cta.shared.b64 _, [%0];" :: "r"(a) : "memory");
}
DI void mbar_expect_tx(uint32_t a, uint32_t bytes) {
    asm volatile("mbarrier.arrive.expect_tx.shared.b64 _, [%0], %1;" :: "r"(a), "r"(bytes) : "memory");
}
DI void mbar_wait(uint32_t a, uint32_t parity) {
    asm volatile(
        "{\n\t"
        ".reg .pred P1;\n\t"
        "WAIT_LOOP_%=:\n\t"
        "mbarrier.try_wait.parity.acquire.cta.shared::cta.b64 P1, [%0], %1, 0x989680;\n\t"
        "@P1 bra.uni WAIT_DONE_%=;\n\t"
        "bra.uni WAIT_LOOP_%=;\n\t"
        "WAIT_DONE_%=:\n\t"
        "}"
        :: "r"(a), "r"(parity) : "memory");
}
DI void bulk_g2s(uint32_t dst, const void* src, uint32_t bytes, uint32_t mbar) {
    asm volatile(
        "cp.async.bulk.shared::cluster.global.mbarrier::complete_tx::bytes [%0], [%1], %2, [%3];"
        :: "r"(dst), "l"(src), "r"(bytes), "r"(mbar) : "memory");
}
DI void ldsm4(uint32_t* r, uint32_t addr) {
    asm volatile("ldmatrix.sync.aligned.m8n8.x4.shared.b16 {%0,%1,%2,%3}, [%4];"
                 : "=r"(r[0]), "=r"(r[1]), "=r"(r[2]), "=r"(r[3]) : "r"(addr));
}
DI void mma_f16(float* c, const uint32_t* a, uint32_t b0, uint32_t b1) {
    asm volatile(
        "mma.sync.aligned.m16n8k16.row.col.f32.f16.f16.f32 "
        "{%0,%1,%2,%3}, {%4,%5,%6,%7}, {%8,%9}, {%0,%1,%2,%3};"
        : "+f"(c[0]), "+f"(c[1]), "+f"(c[2]), "+f"(c[3])
        : "r"(a[0]), "r"(a[1]), "r"(a[2]), "r"(a[3]), "r"(b0), "r"(b1));
}

// ---------------- merged prologue: A (closed-form bases + silu) and B ----------------
__global__ void __launch_bounds__(256) prolog_ab(const float* __restrict__ x,
                                                 const float* __restrict__ spw,
                                                 const float* __restrict__ baw) {
    if (blockIdx.x < BLOCKS_A) {
        // ----- part A: one (b, i) per thread -----
        int idx = blockIdx.x * 256 + threadIdx.x;
        int b = idx >> 10;
        int i = idx & 1023;
        float xv = x[idx];

        // tanh(x) = 1 - 2/(e^{2x}+1)
        float t = 1.0f - __fdividef(2.0f, __expf(2.0f * xv) + 1.0f);

        // closed-form cubic B-spline: only 4 nonzero bases
        float sc = (t + 2.2f) * 2.5f;                  // interval coord, in [3, 8]
        int m = __float2int_rd(sc);
        m = max(3, min(7, m));                          // clamp (t = +-1 edges)
        float u = sc - (float)m;                        // [0, 1)
        float omu = 1.0f - u;
        float B0 = omu * omu * omu * (1.0f / 6.0f);
        float B3 = u * u * u * (1.0f / 6.0f);
        float B1 = (0.5f * u - 1.0f) * u * u + (2.0f / 3.0f);   // 0.5u^3 - u^2 + 2/3
        float B2 = 1.0f - B0 - B1 - B3;                // partition of unity
        int o = m - 3;                                  // 0..4: first nonzero basis index

        uint32_t p01 = __float_as_uint(0.0f);  // placeholder; build half2 pairs
        // pack pairs as half2
        uint32_t hB01, hB23, hB_0, hB3_;
        {
            __half2 v;
            v = __floats2half2_rn(B0, B1); hB01 = *reinterpret_cast<uint32_t*>(&v);
            v = __floats2half2_rn(B2, B3); hB23 = *reinterpret_cast<uint32_t*>(&v);
            v = __floats2half2_rn(0.0f, B0); hB_0 = *reinterpret_cast<uint32_t*>(&v);
            v = __floats2half2_rn(B1, B2); p01 = *reinterpret_cast<uint32_t*>(&v);  // reuse: (B1,B2)
            v = __floats2half2_rn(B3, 0.0f); hB3_ = *reinterpret_cast<uint32_t*>(&v);
        }
        uint4 out4;
        switch (o) {
            case 0: out4 = make_uint4(hB01, hB23, 0u, 0u); break;
            case 1: out4 = make_uint4(hB_0, p01, hB3_, 0u); break;
            case 2: out4 = make_uint4(0u, hB01, hB23, 0u); break;
            case 3: out4 = make_uint4(0u, hB_0, p01, hB3_); break;
            default: out4 = make_uint4(0u, 0u, hB01, hB23); break;  // o==4
        }

        int mt = b >> 7, row = b & 127;
        char* abase = (char*)g_A;
        {
            int kt = i >> 3;
            size_t tile = ((size_t)(mt * NKT + kt)) * A_TILE_B;
            uint32_t off = (uint32_t)(row * 128 + (i & 7) * 16);
            *reinterpret_cast<uint4*>(abase + tile + swz(off)) = out4;
        }
        {
            float sl = __fdividef(xv, 1.0f + __expf(-xv));
            int kt = 128 + (i >> 6);
            size_t tile = ((size_t)(mt * NKT + kt)) * A_TILE_B;
            uint32_t off = (uint32_t)(row * 128 + (i & 63) * 2);
            *reinterpret_cast<__half*>(abase + tile + swz(off)) = __float2half_rn(sl);
        }
    } else {
        // ----- part B: one group of 8 K-floats per thread -----
        int idx = (blockIdx.x - BLOCKS_A) * 256 + threadIdx.x;
        int o  = idx / (KTOT / 8);
        int kq = idx % (KTOT / 8);
        int k  = kq * 8;
        float4 v0, v1;
        if (k < KSP) {
            const float4* p = reinterpret_cast<const float4*>(spw + (size_t)o * KSP + k);
            v0 = p[0]; v1 = p[1];
        } else {
            const float4* p = reinterpret_cast<const float4*>(baw + (size_t)o * INF + (k - KSP));
            v0 = p[0]; v1 = p[1];
        }
        __half hv[8];
        hv[0] = __float2half_rn(v0.x); hv[1] = __float2half_rn(v0.y);
        hv[2] = __float2half_rn(v0.z); hv[3] = __float2half_rn(v0.w);
        hv[4] = __float2half_rn(v1.x); hv[5] = __float2half_rn(v1.y);
        hv[6] = __float2half_rn(v1.z); hv[7] = __float2half_rn(v1.w);

        int nt = o >> 7, row = o & 127;   // TN=128 tiles now
        int kt = k >> 6;
        size_t tile = ((size_t)(nt * NKT + kt)) * B_TILE_B;
        uint32_t off = (uint32_t)(row * 128 + (k & 63) * 2);
        *reinterpret_cast<uint4*>((char*)g_B + tile + swz(off)) = *reinterpret_cast<uint4*>(hv);
    }
}

// ---------------- GEMM: mma.sync fp16, CTA 128x128, 3-stage pipeline, 2 CTAs/SM ----------------
__global__ void __launch_bounds__(256, 2) kan_gemm(float* __restrict__ out) {
    extern __shared__ __align__(16) char smem_raw[];
    uint32_t sb = (s2u(smem_raw) + 1023u) & ~1023u;
    int tid = threadIdx.x, wid = tid >> 5, lane = tid & 31;
    int warp_m = wid >> 2, warp_n = wid & 3;   // 2 x 4 warp grid, 64x32 per warp

    if (tid == 0) {
        for (int s = 0; s < STAGES; s++) {
            mbar_init(sb + SOFF_FULL  + 8 * s, 1);
            mbar_init(sb + SOFF_EMPTY + 8 * s, 256);
        }
    }
    __syncthreads();

    int mt = blockIdx.x, nt = blockIdx.y;
    const char* agl = (const char*)g_A + (size_t)mt * NKT * A_TILE_B;
    const char* bgl = (const char*)g_B + (size_t)nt * NKT * B_TILE_B;

    // ---- per-thread ldmatrix addressing (swizzle-folded) ----
    int g = lane >> 3, r = lane & 7;
    int rA = warp_m * 64 + (g & 1) * 8 + r;
    uint32_t acol0 = (uint32_t)((g >> 1) * 16);
    uint32_t amask = (uint32_t)((rA & 7) << 4);
    int rB = warp_n * 32 + ((g >> 1) & 1) * 8 + r;
    uint32_t bcol0 = (uint32_t)((g & 1) * 16);
    uint32_t bmask = (uint32_t)((rB & 7) << 4);
    uint32_t acol[4], bcol[4];
#pragma unroll
    for (int ks = 0; ks < 4; ks++) {
        acol[ks] = (acol0 + ks * 32) ^ amask;
        bcol[ks] = (bcol0 + ks * 32) ^ bmask;
    }
    uint32_t aRowOff = (uint32_t)(rA * 128);
    uint32_t bRowOff = (uint32_t)(A_TILE_B + rB * 128);

    float acc[4][4][4];
#pragma unroll
    for (int mi = 0; mi < 4; mi++)
#pragma unroll
        for (int nj = 0; nj < 4; nj++)
#pragma unroll
            for (int q = 0; q < 4; q++) acc[mi][nj][q] = 0.0f;

    // ---- prefetch first STAGES-1 tiles ----
    if (tid == 0) {
#pragma unroll
        for (int p = 0; p < STAGES - 1; p++) {
            uint32_t full = sb + SOFF_FULL + 8 * p;
            mbar_expect_tx(full, STAGE_B);
            uint32_t sa = sb + SOFF_STAGE + p * STAGE_B;
            bulk_g2s(sa,            agl + (size_t)p * A_TILE_B, A_TILE_B, full);
            bulk_g2s(sa + A_TILE_B, bgl + (size_t)p * B_TILE_B, B_TILE_B, full);
        }
    }

    int fphase = 0, ephase = 0;
#pragma unroll 1
    for (int kt = 0; kt < NKT; kt++) {
        if (tid == 0) {
            int j = kt + STAGES - 1;
            if (j < NKT) {
                int sp = j % STAGES;
                if (j >= STAGES) {
                    mbar_wait(sb + SOFF_EMPTY + 8 * sp, ephase);
                    if (sp == STAGES - 1) ephase ^= 1;
                }
                uint32_t full = sb + SOFF_FULL + 8 * sp;
                mbar_expect_tx(full, STAGE_B);
                uint32_t sa = sb + SOFF_STAGE + sp * STAGE_B;
                bulk_g2s(sa,            agl + (size_t)j * A_TILE_B, A_TILE_B, full);
                bulk_g2s(sa + A_TILE_B, bgl + (size_t)j * B_TILE_B, B_TILE_B, full);
            }
        }
        int s = kt % STAGES;
        mbar_wait(sb + SOFF_FULL + 8 * s, fphase);
        if (s == STAGES - 1) fphase ^= 1;

        uint32_t sbase = sb + SOFF_STAGE + s * STAGE_B;
        uint32_t baseA = sbase + aRowOff;
        uint32_t baseB = sbase + bRowOff;
#pragma unroll
        for (int ks = 0; ks < 4; ks++) {
            uint32_t af[4][4], bf[2][4];
#pragma unroll
            for (int mi = 0; mi < 4; mi++) ldsm4(af[mi], baseA + mi * 2048 + acol[ks]);
#pragma unroll
            for (int np = 0; np < 2; np++) ldsm4(bf[np], baseB + np * 2048 + bcol[ks]);
            // Early release: stage smem is dead for this thread after its last ldmatrix
            if (ks == 3) mbar_arrive(sb + SOFF_EMPTY + 8 * s);
#pragma unroll
            for (int mi = 0; mi < 4; mi++)
#pragma unroll
                for (int nj = 0; nj < 4; nj++)
                    mma_f16(acc[mi][nj], af[mi],
                            bf[nj >> 1][(nj & 1) * 2], bf[nj >> 1][(nj & 1) * 2 + 1]);
        }
    }

    // ---- epilogue: FP32 accumulators -> global ----
    int row0 = mt * 128 + warp_m * 64 + (lane >> 2);
    int col0 = nt * 128 + warp_n * 32 + (lane & 3) * 2;
#pragma unroll
    for (int mi = 0; mi < 4; mi++) {
#pragma unroll
        for (int nj = 0; nj < 4; nj++) {
            float* p0 = out + (size_t)(row0 + mi * 16) * OUTF + col0 + nj * 8;
            float* p1 = out + (size_t)(row0 + mi * 16 + 8) * OUTF + col0 + nj * 8;
            *reinterpret_cast<float2*>(p0) = make_float2(acc[mi][nj][0], acc[mi][nj][1]);
            *reinterpret_cast<float2*>(p1) = make_float2(acc[mi][nj][2], acc[mi][nj][3]);
        }
    }
}

// ---------------- host launch ----------------
extern "C" void kernel_launch(void* const* d_in, const int* in_sizes, int n_in,
                              void* d_out, int out_size) {
    (void)in_sizes; (void)n_in; (void)out_size;
    const float* x   = (const float*)d_in[0];
    const float* spw = (const float*)d_in[1];
    const float* baw = (const float*)d_in[2];
    float* out = (float*)d_out;

    prolog_ab<<<BLOCKS_A + BLOCKS_B, 256>>>(x, spw, baw);

    static int smem_set = 0;
    if (!smem_set) {
        cudaFuncSetAttribute(kan_gemm, cudaFuncAttributeMaxDynamicSharedMemorySize, SMEM_NEED);
        smem_set = 1;
    }
    kan_gemm<<<dim3(MT, NT), 256, SMEM_NEED>>>(out);
}

// round 9
// speedup vs baseline: 3.3681x; 1.0473x over previous
#include <cuda_runtime.h>
#include <cuda_fp16.h>
#include <cstdint>
#include <cstddef>

#define DI __device__ __forceinline__

// ---------------- problem constants ----------------
constexpr int BATCH = 4096;
constexpr int INF   = 1024;
constexpr int OUTF  = 1024;
constexpr int KSP   = INF * 8;       // 8192 spline K
constexpr int KTOT  = KSP + INF;     // 9216 total K
constexpr int KBLK  = 64;            // fp16 per K-tile -> 128 B rows (SW128)
constexpr int NKT   = KTOT / KBLK;   // 144 K-tiles
constexpr int TM    = 128;
constexpr int TN    = 256;           // proven best: operand reuse beats occupancy
constexpr int MT    = BATCH / TM;    // 32
constexpr int NT    = OUTF / TN;     // 4
constexpr int STAGES = 4;
constexpr int A_TILE_B = TM * KBLK * 2;       // 16384
constexpr int B_TILE_B = TN * KBLK * 2;       // 32768
constexpr int STAGE_B  = A_TILE_B + B_TILE_B; // 49152

constexpr int SOFF_FULL  = 0;    // 4 x 8B
constexpr int SOFF_EMPTY = 32;   // 4 x 8B
constexpr int SOFF_STAGE = 1024;
constexpr int SMEM_NEED  = 1024 + SOFF_STAGE + STAGES * STAGE_B; // 198656 < 227KB cap

constexpr int BLOCKS_A = (BATCH * INF) / 256;       // 16384
constexpr int BLOCKS_B = (OUTF * (KTOT / 8)) / 256; // 4608

// ---------------- scratch (device globals; no allocation) ----------------
__device__ __half g_A[(size_t)MT * NKT * TM * KBLK];  // 75.5 MB tiled+swizzled activations
__device__ __half g_B[(size_t)NT * NKT * TN * KBLK];  // 18.9 MB tiled+swizzled weights

// ---------------- PTX helpers ----------------
DI uint32_t s2u(const void* p) {
    uint32_t a;
    asm("{ .reg .u64 t; cvta.to.shared.u64 t, %1; cvt.u32.u64 %0, t; }" : "=r"(a) : "l"(p));
    return a;
}
DI uint32_t swz(uint32_t off) { return off ^ ((off >> 3) & 0x70); }

DI void mbar_init(uint32_t a, uint32_t cnt) {
    asm volatile("mbarrier.init.shared.b64 [%0], %1;" :: "r"(a), "r"(cnt) : "memory");
}
DI void mbar_arrive(uint32_t a) {
    asm volatile("mbarrier.arrive.release.cta.shared.b64 _, [%0];" :: "r"(a) : "memory");
}
DI void mbar_expect_tx(uint32_t a, uint32_t bytes) {
    asm volatile("mbarrier.arrive.expect_tx.shared.b64 _, [%0], %1;" :: "r"(a), "r"(bytes) : "memory");
}
DI void mbar_wait(uint32_t a, uint32_t parity) {
    asm volatile(
        "{\n\t"
        ".reg .pred P1;\n\t"
        "WAIT_LOOP_%=:\n\t"
        "mbarrier.try_wait.parity.acquire.cta.shared::cta.b64 P1, [%0], %1, 0x989680;\n\t"
        "@P1 bra.uni WAIT_DONE_%=;\n\t"
        "bra.uni WAIT_LOOP_%=;\n\t"
        "WAIT_DONE_%=:\n\t"
        "}"
        :: "r"(a), "r"(parity) : "memory");
}
DI void bulk_g2s(uint32_t dst, const void* src, uint32_t bytes, uint32_t mbar) {
    asm volatile(
        "cp.async.bulk.shared::cluster.global.mbarrier::complete_tx::bytes [%0], [%1], %2, [%3];"
        :: "r"(dst), "l"(src), "r"(bytes), "r"(mbar) : "memory");
}
DI void ldsm4(uint32_t* r, uint32_t addr) {
    asm volatile("ldmatrix.sync.aligned.m8n8.x4.shared.b16 {%0,%1,%2,%3}, [%4];"
                 : "=r"(r[0]), "=r"(r[1]), "=r"(r[2]), "=r"(r[3]) : "r"(addr));
}
DI void mma_f16(float* c, const uint32_t* a, uint32_t b0, uint32_t b1) {
    asm volatile(
        "mma.sync.aligned.m16n8k16.row.col.f32.f16.f16.f32 "
        "{%0,%1,%2,%3}, {%4,%5,%6,%7}, {%8,%9}, {%0,%1,%2,%3};"
        : "+f"(c[0]), "+f"(c[1]), "+f"(c[2]), "+f"(c[3])
        : "r"(a[0]), "r"(a[1]), "r"(a[2]), "r"(a[3]), "r"(b0), "r"(b1));
}

// ---------------- merged prologue: A (closed-form bases + silu) and B ----------------
__global__ void __launch_bounds__(256) prolog_ab(const float* __restrict__ x,
                                                 const float* __restrict__ spw,
                                                 const float* __restrict__ baw) {
    if (blockIdx.x < BLOCKS_A) {
        // ----- part A: one (b, i) per thread -----
        int idx = blockIdx.x * 256 + threadIdx.x;
        int b = idx >> 10;
        int i = idx & 1023;
        float xv = x[idx];

        // tanh(x) = 1 - 2/(e^{2x}+1)
        float t = 1.0f - __fdividef(2.0f, __expf(2.0f * xv) + 1.0f);

        // closed-form cubic B-spline: only 4 nonzero bases
        float sc = (t + 2.2f) * 2.5f;                  // interval coord, in [3, 8]
        int m = __float2int_rd(sc);
        m = max(3, min(7, m));                          // clamp (t = +-1 edges)
        float u = sc - (float)m;                        // [0, 1)
        float omu = 1.0f - u;
        float B0 = omu * omu * omu * (1.0f / 6.0f);
        float B3 = u * u * u * (1.0f / 6.0f);
        float B1 = (0.5f * u - 1.0f) * u * u + (2.0f / 3.0f);   // 0.5u^3 - u^2 + 2/3
        float B2 = 1.0f - B0 - B1 - B3;                // partition of unity
        int o = m - 3;                                  // 0..4: first nonzero basis index

        uint32_t hB01, hB23, hB_0, hB12, hB3_;
        {
            __half2 v;
            v = __floats2half2_rn(B0, B1);   hB01 = *reinterpret_cast<uint32_t*>(&v);
            v = __floats2half2_rn(B2, B3);   hB23 = *reinterpret_cast<uint32_t*>(&v);
            v = __floats2half2_rn(0.0f, B0); hB_0 = *reinterpret_cast<uint32_t*>(&v);
            v = __floats2half2_rn(B1, B2);   hB12 = *reinterpret_cast<uint32_t*>(&v);
            v = __floats2half2_rn(B3, 0.0f); hB3_ = *reinterpret_cast<uint32_t*>(&v);
        }
        uint4 out4;
        switch (o) {
            case 0:  out4 = make_uint4(hB01, hB23, 0u, 0u);   break;
            case 1:  out4 = make_uint4(hB_0, hB12, hB3_, 0u); break;
            case 2:  out4 = make_uint4(0u, hB01, hB23, 0u);   break;
            case 3:  out4 = make_uint4(0u, hB_0, hB12, hB3_); break;
            default: out4 = make_uint4(0u, 0u, hB01, hB23);   break;  // o==4
        }

        int mt = b >> 7, row = b & 127;
        char* abase = (char*)g_A;
        {
            int kt = i >> 3;
            size_t tile = ((size_t)(mt * NKT + kt)) * A_TILE_B;
            uint32_t off = (uint32_t)(row * 128 + (i & 7) * 16);
            *reinterpret_cast<uint4*>(abase + tile + swz(off)) = out4;
        }
        {
            float sl = __fdividef(xv, 1.0f + __expf(-xv));
            int kt = 128 + (i >> 6);
            size_t tile = ((size_t)(mt * NKT + kt)) * A_TILE_B;
            uint32_t off = (uint32_t)(row * 128 + (i & 63) * 2);
            *reinterpret_cast<__half*>(abase + tile + swz(off)) = __float2half_rn(sl);
        }
    } else {
        // ----- part B: one group of 8 K-floats per thread -----
        int idx = (blockIdx.x - BLOCKS_A) * 256 + threadIdx.x;
        int o  = idx / (KTOT / 8);
        int kq = idx % (KTOT / 8);
        int k  = kq * 8;
        float4 v0, v1;
        if (k < KSP) {
            const float4* p = reinterpret_cast<const float4*>(spw + (size_t)o * KSP + k);
            v0 = p[0]; v1 = p[1];
        } else {
            const float4* p = reinterpret_cast<const float4*>(baw + (size_t)o * INF + (k - KSP));
            v0 = p[0]; v1 = p[1];
        }
        __half hv[8];
        hv[0] = __float2half_rn(v0.x); hv[1] = __float2half_rn(v0.y);
        hv[2] = __float2half_rn(v0.z); hv[3] = __float2half_rn(v0.w);
        hv[4] = __float2half_rn(v1.x); hv[5] = __float2half_rn(v1.y);
        hv[6] = __float2half_rn(v1.z); hv[7] = __float2half_rn(v1.w);

        int nt = o >> 8, row = o & 255;   // TN=256 tiles
        int kt = k >> 6;
        size_t tile = ((size_t)(nt * NKT + kt)) * B_TILE_B;
        uint32_t off = (uint32_t)(row * 128 + (k & 63) * 2);
        *reinterpret_cast<uint4*>((char*)g_B + tile + swz(off)) = *reinterpret_cast<uint4*>(hv);
    }
}

// ---------------- GEMM: mma.sync fp16, CTA 128x256, 4-stage pipeline ----------------
__global__ void __launch_bounds__(256, 1) kan_gemm(float* __restrict__ out) {
    extern __shared__ __align__(16) char smem_raw[];
    uint32_t sb = (s2u(smem_raw) + 1023u) & ~1023u;
    int tid = threadIdx.x, wid = tid >> 5, lane = tid & 31;
    int warp_m = wid >> 2, warp_n = wid & 3;   // 2 x 4 warp grid, 64x64 per warp

    if (tid == 0) {
        for (int s = 0; s < STAGES; s++) {
            mbar_init(sb + SOFF_FULL  + 8 * s, 1);
            mbar_init(sb + SOFF_EMPTY + 8 * s, 256);
        }
    }
    __syncthreads();

    int mt = blockIdx.x, nt = blockIdx.y;
    const char* agl = (const char*)g_A + (size_t)mt * NKT * A_TILE_B;
    const char* bgl = (const char*)g_B + (size_t)nt * NKT * B_TILE_B;

    // ---- per-thread ldmatrix addressing (swizzle-folded) ----
    int g = lane >> 3, r = lane & 7;
    int rA = warp_m * 64 + (g & 1) * 8 + r;
    uint32_t acol0 = (uint32_t)((g >> 1) * 16);
    uint32_t amask = (uint32_t)((rA & 7) << 4);
    int rB = warp_n * 64 + ((g >> 1) & 1) * 8 + r;
    uint32_t bcol0 = (uint32_t)((g & 1) * 16);
    uint32_t bmask = (uint32_t)((rB & 7) << 4);
    uint32_t acol[4], bcol[4];
#pragma unroll
    for (int ks = 0; ks < 4; ks++) {
        acol[ks] = (acol0 + ks * 32) ^ amask;
        bcol[ks] = (bcol0 + ks * 32) ^ bmask;
    }
    uint32_t aRowOff = (uint32_t)(rA * 128);
    uint32_t bRowOff = (uint32_t)(A_TILE_B + rB * 128);

    float acc[4][8][4];
#pragma unroll
    for (int mi = 0; mi < 4; mi++)
#pragma unroll
        for (int nj = 0; nj < 8; nj++)
#pragma unroll
            for (int q = 0; q < 4; q++) acc[mi][nj][q] = 0.0f;

    // ---- prefetch first STAGES-1 tiles ----
    if (tid == 0) {
#pragma unroll
        for (int p = 0; p < STAGES - 1; p++) {
            uint32_t full = sb + SOFF_FULL + 8 * p;
            mbar_expect_tx(full, STAGE_B);
            uint32_t sa = sb + SOFF_STAGE + p * STAGE_B;
            bulk_g2s(sa,            agl + (size_t)p * A_TILE_B, A_TILE_B, full);
            bulk_g2s(sa + A_TILE_B, bgl + (size_t)p * B_TILE_B, B_TILE_B, full);
        }
    }

    int fphase = 0, ephase = 0;
#pragma unroll 1
    for (int kt = 0; kt < NKT; kt++) {
        if (tid == 0) {
            int j = kt + STAGES - 1;
            if (j < NKT) {
                int sp = j % STAGES;
                if (j >= STAGES) {
                    mbar_wait(sb + SOFF_EMPTY + 8 * sp, ephase);
                    if (sp == STAGES - 1) ephase ^= 1;
                }
                uint32_t full = sb + SOFF_FULL + 8 * sp;
                mbar_expect_tx(full, STAGE_B);
                uint32_t sa = sb + SOFF_STAGE + sp * STAGE_B;
                bulk_g2s(sa,            agl + (size_t)j * A_TILE_B, A_TILE_B, full);
                bulk_g2s(sa + A_TILE_B, bgl + (size_t)j * B_TILE_B, B_TILE_B, full);
            }
        }
        int s = kt % STAGES;
        mbar_wait(sb + SOFF_FULL + 8 * s, fphase);
        if (s == STAGES - 1) fphase ^= 1;

        uint32_t sbase = sb + SOFF_STAGE + s * STAGE_B;
        uint32_t baseA = sbase + aRowOff;
        uint32_t baseB = sbase + bRowOff;

        // ---- double-buffered fragments across ks sub-steps ----
        uint32_t af[2][4][4], bf[2][4][4];
#pragma unroll
        for (int mi = 0; mi < 4; mi++) ldsm4(af[0][mi], baseA + mi * 2048 + acol[0]);
#pragma unroll
        for (int np = 0; np < 4; np++) ldsm4(bf[0][np], baseB + np * 2048 + bcol[0]);
#pragma unroll
        for (int ks = 0; ks < 4; ks++) {
            int cur = ks & 1, nxt = cur ^ 1;
            if (ks < 3) {
#pragma unroll
                for (int mi = 0; mi < 4; mi++) ldsm4(af[nxt][mi], baseA + mi * 2048 + acol[ks + 1]);
#pragma unroll
                for (int np = 0; np < 4; np++) ldsm4(bf[nxt][np], baseB + np * 2048 + bcol[ks + 1]);
                // all this thread's ldsm for the ktile done after ks==2 prefetch
                if (ks == 2) mbar_arrive(sb + SOFF_EMPTY + 8 * s);
            }
#pragma unroll
            for (int mi = 0; mi < 4; mi++)
#pragma unroll
                for (int nj = 0; nj < 8; nj++)
                    mma_f16(acc[mi][nj], af[cur][mi],
                            bf[cur][nj >> 1][(nj & 1) * 2], bf[cur][nj >> 1][(nj & 1) * 2 + 1]);
        }
    }

    // ---- epilogue: FP32 accumulators -> global ----
    int row0 = mt * 128 + warp_m * 64 + (lane >> 2);
    int col0 = nt * 256 + warp_n * 64 + (lane & 3) * 2;
#pragma unroll
    for (int mi = 0; mi < 4; mi++) {
#pragma unroll
        for (int nj = 0; nj < 8; nj++) {
            float* p0 = out + (size_t)(row0 + mi * 16) * OUTF + col0 + nj * 8;
            float* p1 = out + (size_t)(row0 + mi * 16 + 8) * OUTF + col0 + nj * 8;
            *reinterpret_cast<float2*>(p0) = make_float2(acc[mi][nj][0], acc[mi][nj][1]);
            *reinterpret_cast<float2*>(p1) = make_float2(acc[mi][nj][2], acc[mi][nj][3]);
        }
    }
}

// ---------------- host launch ----------------
extern "C" void kernel_launch(void* const* d_in, const int* in_sizes, int n_in,
                              void* d_out, int out_size) {
    (void)in_sizes; (void)n_in; (void)out_size;
    const float* x   = (const float*)d_in[0];
    const float* spw = (const float*)d_in[1];
    const float* baw = (const float*)d_in[2];
    float* out = (float*)d_out;

    prolog_ab<<<BLOCKS_A + BLOCKS_B, 256>>>(x, spw, baw);

    static int smem_set = 0;
    if (!smem_set) {
        cudaFuncSetAttribute(kan_gemm, cudaFuncAttributeMaxDynamicSharedMemorySize, SMEM_NEED);
        smem_set = 1;
    }
    kan_gemm<<<dim3(MT, NT), 256, SMEM_NEED>>>(out);
}

// round 10
// speedup vs baseline: 3.4526x; 1.0251x over previous
#include <cuda_runtime.h>
#include <cuda_fp16.h>
#include <cstdint>
#include <cstddef>

#define DI __device__ __forceinline__

// ---------------- problem constants ----------------
constexpr int BATCH = 4096;
constexpr int INF   = 1024;
constexpr int OUTF  = 1024;
constexpr int KSP   = INF * 8;       // 8192 spline K
constexpr int KTOT  = KSP + INF;     // 9216 total K
constexpr int KBLK  = 64;            // fp16 per K-tile -> 128 B rows (SW128)
constexpr int NKT   = KTOT / KBLK;   // 144 K-tiles
constexpr int TM    = 128;
constexpr int TN    = 256;           // proven best: operand reuse beats occupancy
constexpr int MT    = BATCH / TM;    // 32
constexpr int NT    = OUTF / TN;     // 4
constexpr int STAGES = 4;
constexpr int A_TILE_B = TM * KBLK * 2;       // 16384
constexpr int B_TILE_B = TN * KBLK * 2;       // 32768
constexpr int STAGE_B  = A_TILE_B + B_TILE_B; // 49152

constexpr int SOFF_FULL  = 0;    // 4 x 8B
constexpr int SOFF_EMPTY = 32;   // 4 x 8B
constexpr int SOFF_STAGE = 1024;
constexpr int SMEM_NEED  = 1024 + SOFF_STAGE + STAGES * STAGE_B; // 198656 < 227KB cap

constexpr int BLOCKS_A = (BATCH * INF) / 256;       // 16384
constexpr int BLOCKS_B = (OUTF * (KTOT / 8)) / 256; // 4608

// ---------------- scratch (device globals; no allocation) ----------------
__device__ __half g_A[(size_t)MT * NKT * TM * KBLK];  // 75.5 MB tiled+swizzled activations
__device__ __half g_B[(size_t)NT * NKT * TN * KBLK];  // 18.9 MB tiled+swizzled weights

// ---------------- PTX helpers ----------------
DI uint32_t s2u(const void* p) {
    uint32_t a;
    asm("{ .reg .u64 t; cvta.to.shared.u64 t, %1; cvt.u32.u64 %0, t; }" : "=r"(a) : "l"(p));
    return a;
}
DI uint32_t swz(uint32_t off) { return off ^ ((off >> 3) & 0x70); }

DI void mbar_init(uint32_t a, uint32_t cnt) {
    asm volatile("mbarrier.init.shared.b64 [%0], %1;" :: "r"(a), "r"(cnt) : "memory");
}
DI void mbar_arrive(uint32_t a) {
    asm volatile("mbarrier.arrive.release.cta.shared.b64 _, [%0];" :: "r"(a) : "memory");
}
DI void mbar_expect_tx(uint32_t a, uint32_t bytes) {
    asm volatile("mbarrier.arrive.expect_tx.shared.b64 _, [%0], %1;" :: "r"(a), "r"(bytes) : "memory");
}
DI void mbar_wait(uint32_t a, uint32_t parity) {
    asm volatile(
        "{\n\t"
        ".reg .pred P1;\n\t"
        "WAIT_LOOP_%=:\n\t"
        "mbarrier.try_wait.parity.acquire.cta.shared::cta.b64 P1, [%0], %1, 0x989680;\n\t"
        "@P1 bra.uni WAIT_DONE_%=;\n\t"
        "bra.uni WAIT_LOOP_%=;\n\t"
        "WAIT_DONE_%=:\n\t"
        "}"
        :: "r"(a), "r"(parity) : "memory");
}
DI void bulk_g2s(uint32_t dst, const void* src, uint32_t bytes, uint32_t mbar) {
    asm volatile(
        "cp.async.bulk.shared::cluster.global.mbarrier::complete_tx::bytes [%0], [%1], %2, [%3];"
        :: "r"(dst), "l"(src), "r"(bytes), "r"(mbar) : "memory");
}
DI void ldsm4(uint32_t* r, uint32_t addr) {
    asm volatile("ldmatrix.sync.aligned.m8n8.x4.shared.b16 {%0,%1,%2,%3}, [%4];"
                 : "=r"(r[0]), "=r"(r[1]), "=r"(r[2]), "=r"(r[3]) : "r"(addr));
}
DI void mma_f16(float* c, const uint32_t* a, uint32_t b0, uint32_t b1) {
    asm volatile(
        "mma.sync.aligned.m16n8k16.row.col.f32.f16.f16.f32 "
        "{%0,%1,%2,%3}, {%4,%5,%6,%7}, {%8,%9}, {%0,%1,%2,%3};"
        : "+f"(c[0]), "+f"(c[1]), "+f"(c[2]), "+f"(c[3])
        : "r"(a[0]), "r"(a[1]), "r"(a[2]), "r"(a[3]), "r"(b0), "r"(b1));
}

// ---------------- merged prologue: A (closed-form bases + silu) and B ----------------
__global__ void __launch_bounds__(256) prolog_ab(const float* __restrict__ x,
                                                 const float* __restrict__ spw,
                                                 const float* __restrict__ baw) {
    if (blockIdx.x < BLOCKS_A) {
        // ----- part A: one (b, i) per thread -----
        int idx = blockIdx.x * 256 + threadIdx.x;
        int b = idx >> 10;
        int i = idx & 1023;
        float xv = x[idx];

        // tanh(x) = 1 - 2/(e^{2x}+1)
        float t = 1.0f - __fdividef(2.0f, __expf(2.0f * xv) + 1.0f);

        // closed-form cubic B-spline: only 4 nonzero bases
        float sc = (t + 2.2f) * 2.5f;                  // interval coord, in [3, 8]
        int m = __float2int_rd(sc);
        m = max(3, min(7, m));                          // clamp (t = +-1 edges)
        float u = sc - (float)m;                        // [0, 1)
        float omu = 1.0f - u;
        float B0 = omu * omu * omu * (1.0f / 6.0f);
        float B3 = u * u * u * (1.0f / 6.0f);
        float B1 = (0.5f * u - 1.0f) * u * u + (2.0f / 3.0f);   // 0.5u^3 - u^2 + 2/3
        float B2 = 1.0f - B0 - B1 - B3;                // partition of unity
        int o = m - 3;                                  // 0..4: first nonzero basis index

        uint32_t hB01, hB23, hB_0, hB12, hB3_;
        {
            __half2 v;
            v = __floats2half2_rn(B0, B1);   hB01 = *reinterpret_cast<uint32_t*>(&v);
            v = __floats2half2_rn(B2, B3);   hB23 = *reinterpret_cast<uint32_t*>(&v);
            v = __floats2half2_rn(0.0f, B0); hB_0 = *reinterpret_cast<uint32_t*>(&v);
            v = __floats2half2_rn(B1, B2);   hB12 = *reinterpret_cast<uint32_t*>(&v);
            v = __floats2half2_rn(B3, 0.0f); hB3_ = *reinterpret_cast<uint32_t*>(&v);
        }
        uint4 out4;
        switch (o) {
            case 0:  out4 = make_uint4(hB01, hB23, 0u, 0u);   break;
            case 1:  out4 = make_uint4(hB_0, hB12, hB3_, 0u); break;
            case 2:  out4 = make_uint4(0u, hB01, hB23, 0u);   break;
            case 3:  out4 = make_uint4(0u, hB_0, hB12, hB3_); break;
            default: out4 = make_uint4(0u, 0u, hB01, hB23);   break;  // o==4
        }

        int mt = b >> 7, row = b & 127;
        char* abase = (char*)g_A;
        {
            int kt = i >> 3;
            size_t tile = ((size_t)(mt * NKT + kt)) * A_TILE_B;
            uint32_t off = (uint32_t)(row * 128 + (i & 7) * 16);
            *reinterpret_cast<uint4*>(abase + tile + swz(off)) = out4;
        }
        {
            float sl = __fdividef(xv, 1.0f + __expf(-xv));
            int kt = 128 + (i >> 6);
            size_t tile = ((size_t)(mt * NKT + kt)) * A_TILE_B;
            uint32_t off = (uint32_t)(row * 128 + (i & 63) * 2);
            *reinterpret_cast<__half*>(abase + tile + swz(off)) = __float2half_rn(sl);
        }
    } else {
        // ----- part B: one group of 8 K-floats per thread -----
        int idx = (blockIdx.x - BLOCKS_A) * 256 + threadIdx.x;
        int o  = idx / (KTOT / 8);
        int kq = idx % (KTOT / 8);
        int k  = kq * 8;
        float4 v0, v1;
        if (k < KSP) {
            const float4* p = reinterpret_cast<const float4*>(spw + (size_t)o * KSP + k);
            v0 = p[0]; v1 = p[1];
        } else {
            const float4* p = reinterpret_cast<const float4*>(baw + (size_t)o * INF + (k - KSP));
            v0 = p[0]; v1 = p[1];
        }
        __half hv[8];
        hv[0] = __float2half_rn(v0.x); hv[1] = __float2half_rn(v0.y);
        hv[2] = __float2half_rn(v0.z); hv[3] = __float2half_rn(v0.w);
        hv[4] = __float2half_rn(v1.x); hv[5] = __float2half_rn(v1.y);
        hv[6] = __float2half_rn(v1.z); hv[7] = __float2half_rn(v1.w);

        int nt = o >> 8, row = o & 255;   // TN=256 tiles
        int kt = k >> 6;
        size_t tile = ((size_t)(nt * NKT + kt)) * B_TILE_B;
        uint32_t off = (uint32_t)(row * 128 + (k & 63) * 2);
        *reinterpret_cast<uint4*>((char*)g_B + tile + swz(off)) = *reinterpret_cast<uint4*>(hv);
    }
}

// ---------------- GEMM: mma.sync fp16, CTA 128x256, 4-stage pipeline ----------------
// Cross-ktile software pipelining: at the ks==3 slot of tile kt, wait full[kt+1]
// and prefetch its ks=0 fragments into the spare buffer so the ktile seam
// (mbar fast-path + first LDSMs) hides under the last two MMA batches.
__global__ void __launch_bounds__(256, 1) kan_gemm(float* __restrict__ out) {
    extern __shared__ __align__(16) char smem_raw[];
    uint32_t sb = (s2u(smem_raw) + 1023u) & ~1023u;
    int tid = threadIdx.x, wid = tid >> 5, lane = tid & 31;
    int warp_m = wid >> 2, warp_n = wid & 3;   // 2 x 4 warp grid, 64x64 per warp

    if (tid == 0) {
        for (int s = 0; s < STAGES; s++) {
            mbar_init(sb + SOFF_FULL  + 8 * s, 1);
            mbar_init(sb + SOFF_EMPTY + 8 * s, 256);
        }
    }
    __syncthreads();

    int mt = blockIdx.x, nt = blockIdx.y;
    const char* agl = (const char*)g_A + (size_t)mt * NKT * A_TILE_B;
    const char* bgl = (const char*)g_B + (size_t)nt * NKT * B_TILE_B;

    // ---- per-thread ldmatrix addressing (swizzle-folded) ----
    int g = lane >> 3, r = lane & 7;
    int rA = warp_m * 64 + (g & 1) * 8 + r;
    uint32_t acol0 = (uint32_t)((g >> 1) * 16);
    uint32_t amask = (uint32_t)((rA & 7) << 4);
    int rB = warp_n * 64 + ((g >> 1) & 1) * 8 + r;
    uint32_t bcol0 = (uint32_t)((g & 1) * 16);
    uint32_t bmask = (uint32_t)((rB & 7) << 4);
    uint32_t acol[4], bcol[4];
#pragma unroll
    for (int ks = 0; ks < 4; ks++) {
        acol[ks] = (acol0 + ks * 32) ^ amask;
        bcol[ks] = (bcol0 + ks * 32) ^ bmask;
    }
    uint32_t aRowOff = (uint32_t)(rA * 128);
    uint32_t bRowOff = (uint32_t)(A_TILE_B + rB * 128);

    float acc[4][8][4];
#pragma unroll
    for (int mi = 0; mi < 4; mi++)
#pragma unroll
        for (int nj = 0; nj < 8; nj++)
#pragma unroll
            for (int q = 0; q < 4; q++) acc[mi][nj][q] = 0.0f;

    // ---- prefetch first STAGES-1 tiles ----
    if (tid == 0) {
#pragma unroll
        for (int p = 0; p < STAGES - 1; p++) {
            uint32_t full = sb + SOFF_FULL + 8 * p;
            mbar_expect_tx(full, STAGE_B);
            uint32_t sa = sb + SOFF_STAGE + p * STAGE_B;
            bulk_g2s(sa,            agl + (size_t)p * A_TILE_B, A_TILE_B, full);
            bulk_g2s(sa + A_TILE_B, bgl + (size_t)p * B_TILE_B, B_TILE_B, full);
        }
    }

    // ---- pipeline prologue: wait stage 0, load its ks=0 fragments ----
    uint32_t af[2][4][4], bf[2][4][4];
    mbar_wait(sb + SOFF_FULL + 0, 0);
    {
        uint32_t baseA = sb + SOFF_STAGE + aRowOff;
        uint32_t baseB = sb + SOFF_STAGE + bRowOff;
#pragma unroll
        for (int mi = 0; mi < 4; mi++) ldsm4(af[0][mi], baseA + mi * 2048 + acol[0]);
#pragma unroll
        for (int np = 0; np < 4; np++) ldsm4(bf[0][np], baseB + np * 2048 + bcol[0]);
    }

    int ephase = 0;
#pragma unroll 1
    for (int kt = 0; kt < NKT; kt++) {
        if (tid == 0) {
            int j = kt + STAGES - 1;
            if (j < NKT) {
                int sp = j % STAGES;
                if (j >= STAGES) {
                    mbar_wait(sb + SOFF_EMPTY + 8 * sp, ephase);
                    if (sp == STAGES - 1) ephase ^= 1;
                }
                uint32_t full = sb + SOFF_FULL + 8 * sp;
                mbar_expect_tx(full, STAGE_B);
                uint32_t sa = sb + SOFF_STAGE + sp * STAGE_B;
                bulk_g2s(sa,            agl + (size_t)j * A_TILE_B, A_TILE_B, full);
                bulk_g2s(sa + A_TILE_B, bgl + (size_t)j * B_TILE_B, B_TILE_B, full);
            }
        }
        int s = kt & (STAGES - 1);
        uint32_t sbase = sb + SOFF_STAGE + s * STAGE_B;
        uint32_t baseA = sbase + aRowOff;
        uint32_t baseB = sbase + bRowOff;

#pragma unroll
        for (int ks = 0; ks < 4; ks++) {
            int cur = ks & 1, nxt = cur ^ 1;
            if (ks < 3) {
#pragma unroll
                for (int mi = 0; mi < 4; mi++) ldsm4(af[nxt][mi], baseA + mi * 2048 + acol[ks + 1]);
#pragma unroll
                for (int np = 0; np < 4; np++) ldsm4(bf[nxt][np], baseB + np * 2048 + bcol[ks + 1]);
                // all of this thread's LDSMs from stage s are done
                if (ks == 2) mbar_arrive(sb + SOFF_EMPTY + 8 * s);
            } else if (kt + 1 < NKT) {
                // cross-tile: wait next stage + prefetch its ks=0 fragments
                int kn = kt + 1;
                int s2 = kn & (STAGES - 1);
                mbar_wait(sb + SOFF_FULL + 8 * s2, (kn >> 2) & 1);
                uint32_t nbase = sb + SOFF_STAGE + s2 * STAGE_B;
#pragma unroll
                for (int mi = 0; mi < 4; mi++) ldsm4(af[nxt][mi], nbase + aRowOff + mi * 2048 + acol[0]);
#pragma unroll
                for (int np = 0; np < 4; np++) ldsm4(bf[nxt][np], nbase + bRowOff + np * 2048 + bcol[0]);
            }
#pragma unroll
            for (int mi = 0; mi < 4; mi++)
#pragma unroll
                for (int nj = 0; nj < 8; nj++)
                    mma_f16(acc[mi][nj], af[cur][mi],
                            bf[cur][nj >> 1][(nj & 1) * 2], bf[cur][nj >> 1][(nj & 1) * 2 + 1]);
        }
    }

    // ---- epilogue: FP32 accumulators -> global ----
    int row0 = mt * 128 + warp_m * 64 + (lane >> 2);
    int col0 = nt * 256 + warp_n * 64 + (lane & 3) * 2;
#pragma unroll
    for (int mi = 0; mi < 4; mi++) {
#pragma unroll
        for (int nj = 0; nj < 8; nj++) {
            float* p0 = out + (size_t)(row0 + mi * 16) * OUTF + col0 + nj * 8;
            float* p1 = out + (size_t)(row0 + mi * 16 + 8) * OUTF + col0 + nj * 8;
            *reinterpret_cast<float2*>(p0) = make_float2(acc[mi][nj][0], acc[mi][nj][1]);
            *reinterpret_cast<float2*>(p1) = make_float2(acc[mi][nj][2], acc[mi][nj][3]);
        }
    }
}

// ---------------- host launch ----------------
extern "C" void kernel_launch(void* const* d_in, const int* in_sizes, int n_in,
                              void* d_out, int out_size) {
    (void)in_sizes; (void)n_in; (void)out_size;
    const float* x   = (const float*)d_in[0];
    const float* spw = (const float*)d_in[1];
    const float* baw = (const float*)d_in[2];
    float* out = (float*)d_out;

    prolog_ab<<<BLOCKS_A + BLOCKS_B, 256>>>(x, spw, baw);

    cudaFuncSetAttribute(kan_gemm, cudaFuncAttributeMaxDynamicSharedMemorySize, SMEM_NEED);
    kan_gemm<<<dim3(MT, NT), 256, SMEM_NEED>>>(out);
}